// round 11
// baseline (speedup 1.0000x reference)
#include <cuda_runtime.h>
#include <cstdint>

// ---------------- problem constants ----------------
#define G_    64
#define T_    8192
#define DIN_  2560
#define DOUT_ 1664
#define CAP_  256

// ---------------- tiling ----------------
#define BM 64
#define BN 256
#define BK 16
#define NK (DIN_ / BK)                 // 160
#define NT_N ((DOUT_ + BN - 1) / BN)   // 7 (last tile masked)

// raw f32 ring: per-converter-thread private slots, stride 11 quads (conflict-free)
#define RS        4
#define RAW_TSTRIDE 176                // 11 * 16 B
#define RAW_STG   (128 * RAW_TSTRIDE)  // 22528
// fp16 ring
#define LDA_B 48                       // A fp16 row stride (32 data + 16 pad)
#define LDB_B 528                      // B fp16 row stride (512 data + 16 pad)
#define FP_A  (BM * LDA_B)             // 3072
#define FP_STG (FP_A + BK * LDB_B)     // 11520
#define NS    8                        // NK % NS == 0

#define SM_MBAR 0                      // full[0..7]@0, empty[0..7]@64
#define SM_RAW  128
#define SM_FP   (SM_RAW + RS * RAW_STG)            // 90240
#define SMEM_TOTAL (SM_FP + NS * FP_STG)           // 182400

#define NCONS 256                      // 8 consumer warps
#define NTHREADS 384                   // + 4 converter warps

__device__ int g_starts[G_];

__global__ void starts_kernel(const int* __restrict__ counts) {
    if (threadIdx.x == 0 && blockIdx.x == 0) {
        int s = 0;
        for (int g = 0; g < G_; ++g) { g_starts[g] = s; s += counts[g]; }
    }
}

static __device__ __forceinline__ uint32_t smem_u32(const void* p) {
    uint32_t a;
    asm("{ .reg .u64 t; cvta.to.shared.u64 t, %1; cvt.u32.u64 %0, t; }" : "=r"(a) : "l"(p));
    return a;
}
static __device__ __forceinline__ uint32_t pack_h2(float lo, float hi) {
    uint32_t d;
    asm("cvt.rn.f16x2.f32 %0, %1, %2;" : "=r"(d) : "f"(hi), "f"(lo));
    return d;
}
static __device__ __forceinline__ void cp16(uint32_t dst, const void* src) {
    asm volatile("cp.async.cg.shared.global [%0], [%1], 16;" :: "r"(dst), "l"(src));
}
#define CP_COMMIT()   asm volatile("cp.async.commit_group;")
#define CP_WAIT(n)    asm volatile("cp.async.wait_group %0;" :: "n"(n) : "memory")

static __device__ __forceinline__ float4 lds128(uint32_t addr) {
    float4 v;
    asm volatile("ld.shared.v4.f32 {%0,%1,%2,%3}, [%4];"
                 : "=f"(v.x), "=f"(v.y), "=f"(v.z), "=f"(v.w) : "r"(addr));
    return v;
}
static __device__ __forceinline__ void sts64(uint32_t addr, uint32_t w0, uint32_t w1) {
    asm volatile("st.shared.v2.b32 [%0], {%1, %2};" :: "r"(addr), "r"(w0), "r"(w1));
}

static __device__ __forceinline__ void mbar_init(uint32_t a, uint32_t c) {
    asm volatile("mbarrier.init.shared.b64 [%0], %1;" :: "r"(a), "r"(c) : "memory");
}
static __device__ __forceinline__ void mbar_arrive(uint32_t a) {
    asm volatile("mbarrier.arrive.shared.b64 _, [%0];" :: "r"(a) : "memory");
}
static __device__ __forceinline__ void mbar_wait(uint32_t a, uint32_t parity) {
    asm volatile(
        "{\n\t.reg .pred P;\n"
        "WL_%=:\n\t"
        "mbarrier.try_wait.parity.acquire.cta.shared::cta.b64 P, [%0], %1, 0x989680;\n\t"
        "@P bra.uni WD_%=;\n\t"
        "bra.uni WL_%=;\n"
        "WD_%=:\n\t}"
        :: "r"(a), "r"(parity) : "memory");
}

#define LDSM4(r, a) \
    asm volatile("ldmatrix.sync.aligned.m8n8.x4.shared.b16 {%0,%1,%2,%3}, [%4];" \
        : "=r"((r)[0]), "=r"((r)[1]), "=r"((r)[2]), "=r"((r)[3]) : "r"(a))
#define LDSM4T(r, a) \
    asm volatile("ldmatrix.sync.aligned.m8n8.x4.trans.shared.b16 {%0,%1,%2,%3}, [%4];" \
        : "=r"((r)[0]), "=r"((r)[1]), "=r"((r)[2]), "=r"((r)[3]) : "r"(a))

static __device__ __forceinline__ void mma_f16(float* c, const uint32_t* a,
                                               uint32_t b0, uint32_t b1) {
    asm volatile(
        "mma.sync.aligned.m16n8k16.row.col.f32.f16.f16.f32 "
        "{%0,%1,%2,%3}, {%4,%5,%6,%7}, {%8,%9}, {%0,%1,%2,%3};\n"
        : "+f"(c[0]), "+f"(c[1]), "+f"(c[2]), "+f"(c[3])
        : "r"(a[0]), "r"(a[1]), "r"(a[2]), "r"(a[3]), "r"(b0), "r"(b1));
}

__global__ __launch_bounds__(NTHREADS, 1)
void grouped_gemm_kernel(const float* __restrict__ X, const float* __restrict__ W,
                         const int* __restrict__ counts, float* __restrict__ Y) {
    extern __shared__ char smem[];

    const int g  = blockIdx.z;
    const int mt = blockIdx.y;
    const int nt = blockIdx.x;
    const int cnt = counts[g];
    if (mt * BM >= cnt) return;
    const int gstart = g_starts[g];

    const int t    = threadIdx.x;
    const int lane = t & 31;
    const uint32_t sBase = smem_u32(smem);

    if (t == 0) {
        #pragma unroll
        for (int s = 0; s < NS; ++s) {
            mbar_init(sBase + SM_MBAR + 8 * s, 4);        // full: 4 converter warps
            mbar_init(sBase + SM_MBAR + 64 + 8 * s, 8);   // empty: 8 consumer warps
        }
    }
    __syncthreads();

    if (t >= NCONS) {
        // ================= CONVERTER (4 warps) =================
        const int pt = t - NCONS;                         // 0..127
        // A: chunks 0,1 -> rows (pt>>2), (pt>>2)+32, kv = pt&3
        const int a_kv = pt & 3;
        const int a_r0 = pt >> 2;
        long long ar0 = (long long)gstart + mt * BM + a_r0;
        long long ar1 = ar0 + 32;
        if (ar0 > T_ - 1) ar0 = T_ - 1;                   // clamp; masked in epilogue
        if (ar1 > T_ - 1) ar1 = T_ - 1;
        const float* Ag0 = X + ar0 * DIN_ + a_kv * 4;
        const float* Ag1 = X + ar1 * DIN_ + a_kv * 4;
        const uint32_t aFp0 = (uint32_t)(a_r0 * LDA_B + a_kv * 8);
        const uint32_t aFp1 = (uint32_t)((a_r0 + 32) * LDA_B + a_kv * 8);

        // B: chunks 2..9 -> k = (pt>>6) + 2*i, nv = pt&63
        const int b_k0 = pt >> 6;                         // 0..1
        const int b_nv = pt & 63;
        int bcol = nt * BN + b_nv * 4;
        if (bcol > DOUT_ - 4) bcol = DOUT_ - 4;           // clamp tail tile
        const float* Bg = W + (long long)g * DIN_ * DOUT_ + bcol;
        const uint32_t bFp = (uint32_t)(b_k0 * LDB_B + b_nv * 8);

        const uint32_t mySlot = sBase + SM_RAW + (uint32_t)(pt * RAW_TSTRIDE);

        auto issue_cp = [&](int kt) {                     // into raw slot kt%RS
            const uint32_t raw = mySlot + (uint32_t)((kt & (RS - 1)) * RAW_STG);
            const int k0 = kt * BK;
            cp16(raw,      Ag0 + k0);
            cp16(raw + 16, Ag1 + k0);
            #pragma unroll
            for (int i = 0; i < 8; ++i)
                cp16(raw + 32 + i * 16, Bg + (long long)(k0 + b_k0 + 2 * i) * DOUT_);
        };

        issue_cp(0); CP_COMMIT();
        issue_cp(1); CP_COMMIT();
        issue_cp(2); CP_COMMIT();
        issue_cp(3); CP_COMMIT();

        for (int kt = 0; kt < NK; ++kt) {
            const int s = kt & (NS - 1);
            if (kt >= NS)                                 // fp16 slot free?
                mbar_wait(sBase + SM_MBAR + 64 + 8 * s, ((kt >> 3) & 1) ^ 1);
            CP_WAIT(RS - 1);                              // my raw chunks for kt done

            const uint32_t raw = mySlot + (uint32_t)((kt & (RS - 1)) * RAW_STG);
            const uint32_t fp  = sBase + SM_FP + (uint32_t)(s * FP_STG);

            float4 v = lds128(raw);
            sts64(fp + aFp0, pack_h2(v.x, v.y), pack_h2(v.z, v.w));
            v = lds128(raw + 16);
            sts64(fp + aFp1, pack_h2(v.x, v.y), pack_h2(v.z, v.w));
            #pragma unroll
            for (int i = 0; i < 8; ++i) {
                float4 b = lds128(raw + 32 + i * 16);
                sts64(fp + FP_A + bFp + (uint32_t)(2 * i * LDB_B),
                      pack_h2(b.x, b.y), pack_h2(b.z, b.w));
            }

            __syncwarp();
            if (lane == 0) mbar_arrive(sBase + SM_MBAR + 8 * s);

            if (kt + RS < NK) issue_cp(kt + RS);          // raw slot kt%RS just read
            CP_COMMIT();                                  // one group per iter (may be empty)
        }
        return;
    }

    // ================= CONSUMER (8 warps, 2M x 4N) =================
    const int wid  = t >> 5;
    const int m0 = (wid & 1) * 32;
    const int n0 = (wid >> 1) * 64;
    const int tg  = lane >> 2;
    const int tig = lane & 3;

    const int l15 = lane & 15;
    const int lhi = lane >> 4;
    uint32_t aoff[2];
    #pragma unroll
    for (int mf = 0; mf < 2; ++mf)
        aoff[mf] = (uint32_t)(SM_FP + (m0 + mf * 16 + l15) * LDA_B + lhi * 16);
    uint32_t boff[4];
    #pragma unroll
    for (int p = 0; p < 4; ++p)
        boff[p] = (uint32_t)(SM_FP + FP_A + l15 * LDB_B + (n0 + p * 16 + lhi * 8) * 2);

    float acc[2][8][4];
    #pragma unroll
    for (int mf = 0; mf < 2; ++mf)
        #pragma unroll
        for (int nf = 0; nf < 8; ++nf)
            #pragma unroll
            for (int i = 0; i < 4; ++i) acc[mf][nf][i] = 0.0f;

    for (int kt = 0; kt < NK; ++kt) {
        const int s = kt & (NS - 1);
        mbar_wait(sBase + SM_MBAR + 8 * s, (kt >> 3) & 1);

        const uint32_t fp = sBase + (uint32_t)(s * FP_STG);
        uint32_t af[2][4], bf[4][4];
        LDSM4(af[0], fp + aoff[0]);
        LDSM4(af[1], fp + aoff[1]);
        #pragma unroll
        for (int p = 0; p < 4; ++p)
            LDSM4T(bf[p], fp + boff[p]);

        #pragma unroll
        for (int p = 0; p < 4; ++p)
            #pragma unroll
            for (int mf = 0; mf < 2; ++mf) {
                mma_f16(acc[mf][2 * p],     af[mf], bf[p][0], bf[p][1]);
                mma_f16(acc[mf][2 * p + 1], af[mf], bf[p][2], bf[p][3]);
            }

        __syncwarp();
        if (lane == 0) mbar_arrive(sBase + SM_MBAR + 64 + 8 * s);
    }

    // ---- epilogue: predicated float2 stores ----
    #pragma unroll
    for (int mf = 0; mf < 2; ++mf) {
        const int r0 = mt * BM + m0 + mf * 16 + tg;
        const int r1 = r0 + 8;
        #pragma unroll
        for (int nf = 0; nf < 8; ++nf) {
            const int col = nt * BN + n0 + nf * 8 + tig * 2;
            if (col < DOUT_) {
                if (r0 < cnt) {
                    float2 v = make_float2(acc[mf][nf][0], acc[mf][nf][1]);
                    *(float2*)&Y[(long long)(gstart + r0) * DOUT_ + col] = v;
                }
                if (r1 < cnt) {
                    float2 v = make_float2(acc[mf][nf][2], acc[mf][nf][3]);
                    *(float2*)&Y[(long long)(gstart + r1) * DOUT_ + col] = v;
                }
            }
        }
    }
}

extern "C" void kernel_launch(void* const* d_in, const int* in_sizes, int n_in,
                              void* d_out, int out_size) {
    const float* x    = (const float*)d_in[0];
    const float* w    = (const float*)d_in[1];
    const int*   cnts = (const int*)d_in[2];
    float* y = (float*)d_out;

    starts_kernel<<<1, 32>>>(cnts);

    cudaFuncSetAttribute(grouped_gemm_kernel,
                         cudaFuncAttributeMaxDynamicSharedMemorySize, SMEM_TOTAL);
    dim3 grid(NT_N, CAP_ / BM, G_);      // (7, 4, 64)
    grouped_gemm_kernel<<<grid, NTHREADS, SMEM_TOTAL>>>(x, w, cnts, y);
}

// round 13
// speedup vs baseline: 1.5381x; 1.5381x over previous
#include <cuda_runtime.h>
#include <cstdint>

// ---------------- problem constants ----------------
#define G_    64
#define T_    8192
#define DIN_  2560
#define DOUT_ 1664
#define CAP_  256

// ---------------- tiling ----------------
#define BM 64
#define BN 256
#define BK 16
#define NK (DIN_ / BK)                 // 160
#define NT_N ((DOUT_ + BN - 1) / BN)   // 7 (last tile masked)

// fp16 ring
#define LDA_B 48                       // A fp16 row stride (32 data + 16 pad)
#define LDB_B 528                      // B fp16 row stride (512 data + 16 pad)
#define FP_A  (BM * LDA_B)             // 3072
#define FP_STG (FP_A + BK * LDB_B)     // 11520
#define NS    7                        // ring depth (named-barrier generations handle wrap)
#define SMEM_TOTAL (NS * FP_STG)       // 80640

#define NCONS 256                      // 8 consumer warps
#define NTHREADS 384                   // + 4 producer warps

// named barriers: full[s] = 1+s, empty[s] = 8+s  (id 0 left for __syncthreads)
#define BAR_SYNC(id)   asm volatile("bar.sync %0, %1;"   :: "r"(id), "r"(NTHREADS) : "memory")
#define BAR_ARRIVE(id) asm volatile("bar.arrive %0, %1;" :: "r"(id), "r"(NTHREADS) : "memory")

__device__ int g_starts[G_];

__global__ void starts_kernel(const int* __restrict__ counts) {
    if (threadIdx.x == 0 && blockIdx.x == 0) {
        int s = 0;
        for (int g = 0; g < G_; ++g) { g_starts[g] = s; s += counts[g]; }
    }
}

static __device__ __forceinline__ uint32_t smem_u32(const void* p) {
    uint32_t a;
    asm("{ .reg .u64 t; cvta.to.shared.u64 t, %1; cvt.u32.u64 %0, t; }" : "=r"(a) : "l"(p));
    return a;
}
static __device__ __forceinline__ uint32_t pack_h2(float lo, float hi) {
    uint32_t d;
    asm("cvt.rn.f16x2.f32 %0, %1, %2;" : "=r"(d) : "f"(hi), "f"(lo));
    return d;
}
static __device__ __forceinline__ float4 ldg_cg(const float* p) {
    float4 v;
    asm volatile("ld.global.cg.v4.f32 {%0,%1,%2,%3}, [%4];"
                 : "=f"(v.x), "=f"(v.y), "=f"(v.z), "=f"(v.w) : "l"(p));
    return v;
}
static __device__ __forceinline__ void sts64(uint32_t addr, uint32_t w0, uint32_t w1) {
    asm volatile("st.shared.v2.b32 [%0], {%1, %2};" :: "r"(addr), "r"(w0), "r"(w1));
}

#define LDSM4(r, a) \
    asm volatile("ldmatrix.sync.aligned.m8n8.x4.shared.b16 {%0,%1,%2,%3}, [%4];" \
        : "=r"((r)[0]), "=r"((r)[1]), "=r"((r)[2]), "=r"((r)[3]) : "r"(a))
#define LDSM4T(r, a) \
    asm volatile("ldmatrix.sync.aligned.m8n8.x4.trans.shared.b16 {%0,%1,%2,%3}, [%4];" \
        : "=r"((r)[0]), "=r"((r)[1]), "=r"((r)[2]), "=r"((r)[3]) : "r"(a))

static __device__ __forceinline__ void mma_f16(float* c, const uint32_t* a,
                                               uint32_t b0, uint32_t b1) {
    asm volatile(
        "mma.sync.aligned.m16n8k16.row.col.f32.f16.f16.f32 "
        "{%0,%1,%2,%3}, {%4,%5,%6,%7}, {%8,%9}, {%0,%1,%2,%3};\n"
        : "+f"(c[0]), "+f"(c[1]), "+f"(c[2]), "+f"(c[3])
        : "r"(a[0]), "r"(a[1]), "r"(a[2]), "r"(a[3]), "r"(b0), "r"(b1));
}

__global__ __launch_bounds__(NTHREADS, 1)
void grouped_gemm_kernel(const float* __restrict__ X, const float* __restrict__ W,
                         const int* __restrict__ counts, float* __restrict__ Y) {
    extern __shared__ char smem[];

    const int g  = blockIdx.z;
    const int mt = blockIdx.y;
    const int nt = blockIdx.x;
    const int cnt = counts[g];
    if (mt * BM >= cnt) return;
    const int gstart = g_starts[g];

    const int t    = threadIdx.x;
    const int lane = t & 31;
    const uint32_t sBase = smem_u32(smem);

    if (t >= NCONS) {
        // ================= PRODUCER (4 warps, register-pipelined LDG) =================
        const int pt = t - NCONS;                         // 0..127
        // A: 2 float4/thread -> rows (pt>>2), (pt>>2)+32, kv = pt&3
        const int a_kv = pt & 3;
        const int a_r0 = pt >> 2;
        long long ar0 = (long long)gstart + mt * BM + a_r0;
        long long ar1 = ar0 + 32;
        if (ar0 > T_ - 1) ar0 = T_ - 1;                   // clamp; masked in epilogue
        if (ar1 > T_ - 1) ar1 = T_ - 1;
        const float* Ag0 = X + ar0 * DIN_ + a_kv * 4;
        const float* Ag1 = X + ar1 * DIN_ + a_kv * 4;
        const uint32_t aFp0 = (uint32_t)(a_r0 * LDA_B + a_kv * 8);
        const uint32_t aFp1 = (uint32_t)((a_r0 + 32) * LDA_B + a_kv * 8);

        // B: 8 float4/thread -> k = (pt>>6) + 2*i, nv = pt&63
        const int b_k0 = pt >> 6;                         // 0..1
        const int b_nv = pt & 63;
        int bcol = nt * BN + b_nv * 4;
        if (bcol > DOUT_ - 4) bcol = DOUT_ - 4;           // clamp tail tile
        const float* Bg = W + (long long)g * DIN_ * DOUT_ + bcol;
        const uint32_t bFp = (uint32_t)(b_k0 * LDB_B + b_nv * 8);

        float4 bufA0[2], bufA1[2], bufB[2][8];            // 2-stage register pipeline

        auto load_into = [&](int kt, int slot) {
            const int k0 = kt * BK;
            bufA0[slot] = ldg_cg(Ag0 + k0);
            bufA1[slot] = ldg_cg(Ag1 + k0);
            #pragma unroll
            for (int i = 0; i < 8; ++i)
                bufB[slot][i] = ldg_cg(Bg + (long long)(k0 + b_k0 + 2 * i) * DOUT_);
        };
        auto store_from = [&](int kt, int slot) {
            const uint32_t fp = sBase + (uint32_t)((kt % NS) * FP_STG);
            sts64(fp + aFp0, pack_h2(bufA0[slot].x, bufA0[slot].y),
                             pack_h2(bufA0[slot].z, bufA0[slot].w));
            sts64(fp + aFp1, pack_h2(bufA1[slot].x, bufA1[slot].y),
                             pack_h2(bufA1[slot].z, bufA1[slot].w));
            #pragma unroll
            for (int i = 0; i < 8; ++i)
                sts64(fp + FP_A + bFp + (uint32_t)(2 * i * LDB_B),
                      pack_h2(bufB[slot][i].x, bufB[slot][i].y),
                      pack_h2(bufB[slot][i].z, bufB[slot][i].w));
        };

        load_into(0, 0);
        load_into(1, 1);

        int s = 0;
        #pragma unroll 2
        for (int kt = 0; kt < NK; ++kt) {
            if (kt >= NS) BAR_SYNC(8 + s);                // consumers freed slot s (prev round)
            store_from(kt, kt & 1);
            BAR_ARRIVE(1 + s);                            // slot s full
            if (kt + 2 < NK) load_into(kt + 2, kt & 1);   // refill reg slot; use-distance = 2 stages
            if (++s == NS) s = 0;
        }
        return;
    }

    // ================= CONSUMER (8 warps, 2M x 4N) =================
    const int wid  = t >> 5;
    const int m0 = (wid & 1) * 32;
    const int n0 = (wid >> 1) * 64;
    const int tg  = lane >> 2;
    const int tig = lane & 3;

    const int l15 = lane & 15;
    const int lhi = lane >> 4;
    uint32_t aoff[2];
    #pragma unroll
    for (int mf = 0; mf < 2; ++mf)
        aoff[mf] = (uint32_t)((m0 + mf * 16 + l15) * LDA_B + lhi * 16);
    uint32_t boff[4];
    #pragma unroll
    for (int p = 0; p < 4; ++p)
        boff[p] = (uint32_t)(FP_A + l15 * LDB_B + (n0 + p * 16 + lhi * 8) * 2);

    float acc[2][8][4];
    #pragma unroll
    for (int mf = 0; mf < 2; ++mf)
        #pragma unroll
        for (int nf = 0; nf < 8; ++nf)
            #pragma unroll
            for (int i = 0; i < 4; ++i) acc[mf][nf][i] = 0.0f;

    int s = 0;
    for (int kt = 0; kt < NK; ++kt) {
        BAR_SYNC(1 + s);                                  // slot s full

        const uint32_t fp = sBase + (uint32_t)(s * FP_STG);
        uint32_t af[2][4], bf[4][4];
        LDSM4(af[0], fp + aoff[0]);
        LDSM4(af[1], fp + aoff[1]);
        #pragma unroll
        for (int p = 0; p < 4; ++p)
            LDSM4T(bf[p], fp + boff[p]);

        BAR_ARRIVE(8 + s);                                // frags in regs -> slot s free

        #pragma unroll
        for (int p = 0; p < 4; ++p)
            #pragma unroll
            for (int mf = 0; mf < 2; ++mf) {
                mma_f16(acc[mf][2 * p],     af[mf], bf[p][0], bf[p][1]);
                mma_f16(acc[mf][2 * p + 1], af[mf], bf[p][2], bf[p][3]);
            }
        if (++s == NS) s = 0;
    }

    // ---- epilogue: predicated float2 stores ----
    #pragma unroll
    for (int mf = 0; mf < 2; ++mf) {
        const int r0 = mt * BM + m0 + mf * 16 + tg;
        const int r1 = r0 + 8;
        #pragma unroll
        for (int nf = 0; nf < 8; ++nf) {
            const int col = nt * BN + n0 + nf * 8 + tig * 2;
            if (col < DOUT_) {
                if (r0 < cnt) {
                    float2 v = make_float2(acc[mf][nf][0], acc[mf][nf][1]);
                    *(float2*)&Y[(long long)(gstart + r0) * DOUT_ + col] = v;
                }
                if (r1 < cnt) {
                    float2 v = make_float2(acc[mf][nf][2], acc[mf][nf][3]);
                    *(float2*)&Y[(long long)(gstart + r1) * DOUT_ + col] = v;
                }
            }
        }
    }
}

extern "C" void kernel_launch(void* const* d_in, const int* in_sizes, int n_in,
                              void* d_out, int out_size) {
    const float* x    = (const float*)d_in[0];
    const float* w    = (const float*)d_in[1];
    const int*   cnts = (const int*)d_in[2];
    float* y = (float*)d_out;

    starts_kernel<<<1, 32>>>(cnts);

    cudaFuncSetAttribute(grouped_gemm_kernel,
                         cudaFuncAttributeMaxDynamicSharedMemorySize, SMEM_TOTAL);
    dim3 grid(NT_N, CAP_ / BM, G_);      // (7, 4, 64)
    grouped_gemm_kernel<<<grid, NTHREADS, SMEM_TOTAL>>>(x, w, cnts, y);
}